// round 2
// baseline (speedup 1.0000x reference)
#include <cuda_runtime.h>
#include <math.h>

#define F 256
#define NN 4096
#define TT 8

// ---------------- scratch (no allocations allowed) ----------------
__device__ float g_sn[2];
__device__ float g_Q[2 * 2 * F * F];   // [layer][pingpong][F*F]
__device__ float g_zt[F * F];
__device__ float g_upd[F * F];
__device__ float g_rst[F * F];
__device__ float g_whz[F * F];
__device__ float g_Y[NN * F];
__device__ float g_h1[NN * F];

// ---------------- scorer norms ----------------
__global__ void __launch_bounds__(256) sn_kernel(const float* __restrict__ s0,
                                                 const float* __restrict__ s1) {
    const float* s = (blockIdx.x == 0) ? s0 : s1;
    float p = s[threadIdx.x];
    p = p * p;
#pragma unroll
    for (int o = 16; o > 0; o >>= 1) p += __shfl_xor_sync(0xffffffffu, p, o);
    __shared__ float ws[8];
    if ((threadIdx.x & 31) == 0) ws[threadIdx.x >> 5] = p;
    __syncthreads();
    if (threadIdx.x == 0) {
        float sum = 0.f;
#pragma unroll
        for (int i = 0; i < 8; i++) sum += ws[i];
        g_sn[blockIdx.x] = sqrtf(sum);
    }
}

// ---------------- zt = (embs * tanh(embs@scorer / sn))[:256].T ----------------
// one block per node n (n < 256), 256 threads over features
__global__ void __launch_bounds__(256) zt_kernel(const float* __restrict__ embs,
                                                 const float* __restrict__ scorer,
                                                 int layer, float* __restrict__ ztout) {
    const int n = blockIdx.x;
    const int f = threadIdx.x;
    float v = embs[n * F + f];
    float p = v * scorer[f];
#pragma unroll
    for (int o = 16; o > 0; o >>= 1) p += __shfl_xor_sync(0xffffffffu, p, o);
    __shared__ float ws[8];
    __shared__ float tval;
    if ((f & 31) == 0) ws[f >> 5] = p;
    __syncthreads();
    if (f == 0) {
        float s = 0.f;
#pragma unroll
        for (int i = 0; i < 8; i++) s += ws[i];
        tval = tanhf(s / g_sn[layer]);
    }
    __syncthreads();
    ztout[f * F + n] = v * tval;
}

// ---------------- generic SGEMM: C = [relu](A @ B), row-major ----------------
// block tile 128(M) x 64(N), K-tile 16, 256 threads, 8x4 per thread
__global__ void __launch_bounds__(256) sgemm_kernel(const float* __restrict__ A,
                                                    const float* __restrict__ B,
                                                    float* __restrict__ C,
                                                    int M, int N, int K, int do_relu) {
    __shared__ float As[16][128];
    __shared__ float Bs[16][64];
    const int bm = blockIdx.y * 128;
    const int bn = blockIdx.x * 64;
    const int tid = threadIdx.x;
    const int tx = tid & 15;
    const int ty = tid >> 4;

    float acc[8][4];
#pragma unroll
    for (int i = 0; i < 8; i++)
#pragma unroll
        for (int j = 0; j < 4; j++) acc[i][j] = 0.f;

    const int arow0 = tid >> 2;        // 0..63
    const int akk   = (tid & 3) << 2;  // 0,4,8,12
    const int brow  = tid >> 4;        // 0..15
    const int bnn   = (tid & 15) << 2; // 0..60

    for (int k0 = 0; k0 < K; k0 += 16) {
#pragma unroll
        for (int i = 0; i < 2; i++) {
            const int row = arow0 + i * 64;
            float4 v = *(const float4*)(A + (size_t)(bm + row) * K + (k0 + akk));
            As[akk + 0][row] = v.x;
            As[akk + 1][row] = v.y;
            As[akk + 2][row] = v.z;
            As[akk + 3][row] = v.w;
        }
        {
            float4 v = *(const float4*)(B + (size_t)(k0 + brow) * N + (bn + bnn));
            *(float4*)(&Bs[brow][bnn]) = v;
        }
        __syncthreads();
#pragma unroll
        for (int k = 0; k < 16; k++) {
            float4 a0 = *(const float4*)(&As[k][ty * 8]);
            float4 a1 = *(const float4*)(&As[k][ty * 8 + 4]);
            float4 bv = *(const float4*)(&Bs[k][tx * 4]);
            float a[8] = {a0.x, a0.y, a0.z, a0.w, a1.x, a1.y, a1.z, a1.w};
            float b[4] = {bv.x, bv.y, bv.z, bv.w};
#pragma unroll
            for (int i = 0; i < 8; i++)
#pragma unroll
                for (int j = 0; j < 4; j++) acc[i][j] += a[i] * b[j];
        }
        __syncthreads();
    }
#pragma unroll
    for (int i = 0; i < 8; i++) {
        float4 v;
        v.x = acc[i][0]; v.y = acc[i][1]; v.z = acc[i][2]; v.w = acc[i][3];
        if (do_relu) {
            v.x = fmaxf(v.x, 0.f); v.y = fmaxf(v.y, 0.f);
            v.z = fmaxf(v.z, 0.f); v.w = fmaxf(v.w, 0.f);
        }
        *(float4*)(C + (size_t)(bm + ty * 8 + i) * N + bn + tx * 4) = v;
    }
}

// ---------------- GRU stage 1: upd=sig(Wz@zt+Uz@Q+bz), rst=sig(Wr@zt+Ur@Q+br), whz=Wh@zt+bh
// grid (4,4,3): z = gate; 64x64 tiles, 4x4 per thread
__global__ void __launch_bounds__(256) gru_stage1_kernel(
    const float* __restrict__ Wz, const float* __restrict__ Uz, const float* __restrict__ bz,
    const float* __restrict__ Wr, const float* __restrict__ Ur, const float* __restrict__ br,
    const float* __restrict__ Wh, const float* __restrict__ bh,
    const float* __restrict__ zt, const float* __restrict__ Q,
    float* __restrict__ upd, float* __restrict__ rst, float* __restrict__ whz) {
    const int gate = blockIdx.z;
    const float *A1, *A2, *bias;
    float* out;
    if (gate == 0)      { A1 = Wz; A2 = Uz; bias = bz; out = upd; }
    else if (gate == 1) { A1 = Wr; A2 = Ur; bias = br; out = rst; }
    else                { A1 = Wh; A2 = nullptr; bias = bh; out = whz; }

    __shared__ float A1s[16][64], B1s[16][64], A2s[16][64], B2s[16][64];
    const int bm = blockIdx.y * 64, bn = blockIdx.x * 64;
    const int tid = threadIdx.x, tx = tid & 15, ty = tid >> 4;
    const int arow = tid >> 2, akk = (tid & 3) << 2;
    const int brow = tid >> 4, bnn = (tid & 15) << 2;

    float acc[4][4];
#pragma unroll
    for (int i = 0; i < 4; i++)
#pragma unroll
        for (int j = 0; j < 4; j++) acc[i][j] = 0.f;

    for (int k0 = 0; k0 < F; k0 += 16) {
        {
            float4 v = *(const float4*)(A1 + (size_t)(bm + arow) * F + k0 + akk);
            A1s[akk + 0][arow] = v.x; A1s[akk + 1][arow] = v.y;
            A1s[akk + 2][arow] = v.z; A1s[akk + 3][arow] = v.w;
            float4 w = *(const float4*)(zt + (size_t)(k0 + brow) * F + bn + bnn);
            *(float4*)(&B1s[brow][bnn]) = w;
        }
        if (gate < 2) {
            float4 v = *(const float4*)(A2 + (size_t)(bm + arow) * F + k0 + akk);
            A2s[akk + 0][arow] = v.x; A2s[akk + 1][arow] = v.y;
            A2s[akk + 2][arow] = v.z; A2s[akk + 3][arow] = v.w;
            float4 w = *(const float4*)(Q + (size_t)(k0 + brow) * F + bn + bnn);
            *(float4*)(&B2s[brow][bnn]) = w;
        }
        __syncthreads();
        if (gate < 2) {
#pragma unroll
            for (int k = 0; k < 16; k++) {
                float4 a1 = *(const float4*)(&A1s[k][ty * 4]);
                float4 b1 = *(const float4*)(&B1s[k][tx * 4]);
                float4 a2 = *(const float4*)(&A2s[k][ty * 4]);
                float4 b2 = *(const float4*)(&B2s[k][tx * 4]);
                float av1[4] = {a1.x, a1.y, a1.z, a1.w};
                float bv1[4] = {b1.x, b1.y, b1.z, b1.w};
                float av2[4] = {a2.x, a2.y, a2.z, a2.w};
                float bv2[4] = {b2.x, b2.y, b2.z, b2.w};
#pragma unroll
                for (int i = 0; i < 4; i++)
#pragma unroll
                    for (int j = 0; j < 4; j++)
                        acc[i][j] += av1[i] * bv1[j] + av2[i] * bv2[j];
            }
        } else {
#pragma unroll
            for (int k = 0; k < 16; k++) {
                float4 a1 = *(const float4*)(&A1s[k][ty * 4]);
                float4 b1 = *(const float4*)(&B1s[k][tx * 4]);
                float av1[4] = {a1.x, a1.y, a1.z, a1.w};
                float bv1[4] = {b1.x, b1.y, b1.z, b1.w};
#pragma unroll
                for (int i = 0; i < 4; i++)
#pragma unroll
                    for (int j = 0; j < 4; j++) acc[i][j] += av1[i] * bv1[j];
            }
        }
        __syncthreads();
    }
#pragma unroll
    for (int i = 0; i < 4; i++)
#pragma unroll
        for (int j = 0; j < 4; j++) {
            const int gm = bm + ty * 4 + i;
            const int gn = bn + tx * 4 + j;
            float v = acc[i][j] + bias[gm * F + gn];
            if (gate < 2) v = 1.f / (1.f + expf(-v));
            out[gm * F + gn] = v;
        }
}

// ---------------- GRU stage 2: hcap = tanh(whz + Uh@(rst*Q)); Qn = (1-u)Q + u*hcap
__global__ void __launch_bounds__(256) gru_stage2_kernel(
    const float* __restrict__ Uh, const float* __restrict__ Q,
    const float* __restrict__ rst, const float* __restrict__ upd,
    const float* __restrict__ whz, float* __restrict__ Qn) {
    __shared__ float As[16][64], Bs[16][64];
    const int bm = blockIdx.y * 64, bn = blockIdx.x * 64;
    const int tid = threadIdx.x, tx = tid & 15, ty = tid >> 4;
    const int arow = tid >> 2, akk = (tid & 3) << 2;
    const int brow = tid >> 4, bnn = (tid & 15) << 2;

    float acc[4][4];
#pragma unroll
    for (int i = 0; i < 4; i++)
#pragma unroll
        for (int j = 0; j < 4; j++) acc[i][j] = 0.f;

    for (int k0 = 0; k0 < F; k0 += 16) {
        {
            float4 v = *(const float4*)(Uh + (size_t)(bm + arow) * F + k0 + akk);
            As[akk + 0][arow] = v.x; As[akk + 1][arow] = v.y;
            As[akk + 2][arow] = v.z; As[akk + 3][arow] = v.w;
            float4 r = *(const float4*)(rst + (size_t)(k0 + brow) * F + bn + bnn);
            float4 q = *(const float4*)(Q + (size_t)(k0 + brow) * F + bn + bnn);
            float4 w;
            w.x = r.x * q.x; w.y = r.y * q.y; w.z = r.z * q.z; w.w = r.w * q.w;
            *(float4*)(&Bs[brow][bnn]) = w;
        }
        __syncthreads();
#pragma unroll
        for (int k = 0; k < 16; k++) {
            float4 a = *(const float4*)(&As[k][ty * 4]);
            float4 b = *(const float4*)(&Bs[k][tx * 4]);
            float av[4] = {a.x, a.y, a.z, a.w};
            float bv[4] = {b.x, b.y, b.z, b.w};
#pragma unroll
            for (int i = 0; i < 4; i++)
#pragma unroll
                for (int j = 0; j < 4; j++) acc[i][j] += av[i] * bv[j];
        }
        __syncthreads();
    }
#pragma unroll
    for (int i = 0; i < 4; i++)
#pragma unroll
        for (int j = 0; j < 4; j++) {
            const int idx = (bm + ty * 4 + i) * F + bn + tx * 4 + j;
            float h = tanhf(acc[i][j] + whz[idx]);
            float u = upd[idx];
            Qn[idx] = (1.f - u) * Q[idx] + u * h;
        }
}

// ---------------- orchestration ----------------
extern "C" void kernel_launch(void* const* d_in, const int* in_sizes, int n_in,
                              void* d_out, int out_size) {
    const float* in[25];
    for (int i = 0; i < 25; i++) in[i] = (const float*)d_in[i];
    const float* A = in[0];
    const float* X = in[1];
    // 3: l0_scorer, 4..13: l0 Wz Uz bz Wr Ur br Wh Uh bh Q0
    // 14: l1_scorer, 15..24: l1 Wz Uz bz Wr Ur br Wh Uh bh Q0

    float *Qb, *zt, *upd, *rst, *whz, *Y, *h1;
    cudaGetSymbolAddress((void**)&Qb, g_Q);
    cudaGetSymbolAddress((void**)&zt, g_zt);
    cudaGetSymbolAddress((void**)&upd, g_upd);
    cudaGetSymbolAddress((void**)&rst, g_rst);
    cudaGetSymbolAddress((void**)&whz, g_whz);
    cudaGetSymbolAddress((void**)&Y, g_Y);
    cudaGetSymbolAddress((void**)&h1, g_h1);

    sn_kernel<<<2, 256>>>(in[3], in[14]);

    for (int t = 0; t < TT; t++) {
        const float* embs0 = X + (size_t)t * NN * F;
        const float* At = A + (size_t)t * NN * NN;

        // ---- layer 0 ----
        const float* q0in = (t == 0) ? in[13] : Qb + (size_t)(0 * 2 + ((t - 1) & 1)) * F * F;
        float* q0out = Qb + (size_t)(0 * 2 + (t & 1)) * F * F;
        zt_kernel<<<256, 256>>>(embs0, in[3], 0, zt);
        gru_stage1_kernel<<<dim3(4, 4, 3), 256>>>(in[4], in[5], in[6], in[7], in[8], in[9],
                                                  in[10], in[12], zt, q0in, upd, rst, whz);
        gru_stage2_kernel<<<dim3(4, 4), 256>>>(in[11], q0in, rst, upd, whz, q0out);
        // Y = embs0 @ Qn  [4096,256]
        sgemm_kernel<<<dim3(4, 32), 256>>>(embs0, q0out, Y, NN, F, F, 0);
        // h1 = relu(A[t] @ Y); for t<7 only the first 256 rows are ever consumed
        const int Mrows = (t == TT - 1) ? NN : F;
        sgemm_kernel<<<dim3(4, Mrows / 128), 256>>>(At, Y, h1, Mrows, F, NN, 1);

        // ---- layer 1 ----
        const float* q1in = (t == 0) ? in[24] : Qb + (size_t)(2 + ((t - 1) & 1)) * F * F;
        float* q1out = Qb + (size_t)(2 + (t & 1)) * F * F;
        zt_kernel<<<256, 256>>>(h1, in[14], 1, zt);
        gru_stage1_kernel<<<dim3(4, 4, 3), 256>>>(in[15], in[16], in[17], in[18], in[19],
                                                  in[20], in[21], in[23], zt, q1in, upd, rst, whz);
        gru_stage2_kernel<<<dim3(4, 4), 256>>>(in[22], q1in, rst, upd, whz, q1out);

        if (t == TT - 1) {
            // final output: relu(A[7] @ (h1 @ Qn1))
            sgemm_kernel<<<dim3(4, 32), 256>>>(h1, q1out, Y, NN, F, F, 0);
            sgemm_kernel<<<dim3(4, 32), 256>>>(At, Y, (float*)d_out, NN, F, NN, 1);
        }
    }
}

// round 5
// speedup vs baseline: 1.4538x; 1.4538x over previous
#include <cuda_runtime.h>
#include <math.h>

#define F 256
#define NN 4096
#define TT 8

// ---------------- scratch (no allocations allowed) ----------------
__device__ float g_sn[2];
__device__ float g_Q[2 * 2 * F * F];   // [layer][pingpong][F*F]
__device__ float g_P[7 * F * F];       // P[t] = A[t][0:256,:] @ X[t]
__device__ float g_Y[NN * F];
__device__ float g_h1[NN * F];

// ---------------- scorer norms ----------------
__global__ void __launch_bounds__(256) sn_kernel(const float* __restrict__ s0,
                                                 const float* __restrict__ s1) {
    const float* s = (blockIdx.x == 0) ? s0 : s1;
    float p = s[threadIdx.x];
    p = p * p;
#pragma unroll
    for (int o = 16; o > 0; o >>= 1) p += __shfl_xor_sync(0xffffffffu, p, o);
    __shared__ float ws[8];
    if ((threadIdx.x & 31) == 0) ws[threadIdx.x >> 5] = p;
    __syncthreads();
    if (threadIdx.x == 0) {
        float sum = 0.f;
#pragma unroll
        for (int i = 0; i < 8; i++) sum += ws[i];
        g_sn[blockIdx.x] = sqrtf(sum);
    }
}

// ---------------- batched P[t] = A[t][0:256,:] @ X[t]  (t = 0..6) ----------------
// tile 32(M) x 64(N), K = 4096, grid (4, 8, 7), 256 threads, 2x4 per thread
__global__ void __launch_bounds__(256) pbatch_kernel(const float* __restrict__ A,
                                                     const float* __restrict__ X,
                                                     float* __restrict__ Pout) {
    const int t = blockIdx.z;
    const float* Ap = A + (size_t)t * NN * NN;
    const float* Bp = X + (size_t)t * NN * F;
    float* Cp = Pout + (size_t)t * F * F;

    __shared__ float As2[32][16];
    __shared__ float Bs[16][64];
    const int bm = blockIdx.y * 32;
    const int bn = blockIdx.x * 64;
    const int tid = threadIdx.x;
    const int tx = tid & 15;
    const int ty = tid >> 4;

    float acc[2][4];
#pragma unroll
    for (int i = 0; i < 2; i++)
#pragma unroll
        for (int j = 0; j < 4; j++) acc[i][j] = 0.f;

    const int arow = tid >> 3;
    const int akk = (tid & 7) * 2;
    const int brow = tid >> 4;
    const int bcol = (tid & 15) * 4;

    for (int k0 = 0; k0 < NN; k0 += 16) {
        float2 av = *(const float2*)(Ap + (size_t)(bm + arow) * NN + k0 + akk);
        As2[arow][akk] = av.x;
        As2[arow][akk + 1] = av.y;
        *(float4*)&Bs[brow][bcol] = *(const float4*)(Bp + (size_t)(k0 + brow) * F + bn + bcol);
        __syncthreads();
#pragma unroll
        for (int kk = 0; kk < 16; kk++) {
            float a0 = As2[ty * 2][kk];
            float a1 = As2[ty * 2 + 1][kk];
            float4 b = *(const float4*)&Bs[kk][tx * 4];
            acc[0][0] += a0 * b.x; acc[0][1] += a0 * b.y;
            acc[0][2] += a0 * b.z; acc[0][3] += a0 * b.w;
            acc[1][0] += a1 * b.x; acc[1][1] += a1 * b.y;
            acc[1][2] += a1 * b.z; acc[1][3] += a1 * b.w;
        }
        __syncthreads();
    }
#pragma unroll
    for (int i = 0; i < 2; i++) {
        float4 v;
        v.x = acc[i][0]; v.y = acc[i][1]; v.z = acc[i][2]; v.w = acc[i][3];
        *(float4*)(Cp + (size_t)(bm + ty * 2 + i) * F + bn + tx * 4) = v;
    }
}

// ---------------- fused matrix-GRU step (one launch per layer per timestep) -----
// Column-strip decomposition: each block owns a 4-wide column strip of the
// [256,256] Q matrix. Computes (optionally) h_top = relu(P @ Q0cur), then
// zt, then upd/rst/whz, then stage2 Uh@(rst*Q) and the Q update — all local
// to the strip. Weights streamed from L2 through smem k-tiles of 8.
__global__ void __launch_bounds__(256) gru_kernel(
    const float* __restrict__ embs,   // mode0: rows n0.. feed zt (null in mode1)
    const float* __restrict__ P,      // mode1: [256,256]; null => mode0
    const float* __restrict__ Q0cur,  // mode1: layer-0 current Q
    const float* __restrict__ scorer, int layer,
    const float* __restrict__ Wz, const float* __restrict__ Uz, const float* __restrict__ bz,
    const float* __restrict__ Wr, const float* __restrict__ Ur, const float* __restrict__ br,
    const float* __restrict__ Wh, const float* __restrict__ Uh, const float* __restrict__ bh,
    const float* __restrict__ Qin, float* __restrict__ Qout) {

    __shared__ float zts[256][4];
    __shared__ float qs[256][4];
    __shared__ float rqs[256][4];
    __shared__ float wt[8][256];
    __shared__ float ut[8][256];
    __shared__ float hs[4][256];
    __shared__ float ps[4][256];
    __shared__ float tvalS[4];

    const int tid = threadIdx.x;
    const int n0 = blockIdx.x * 4;
    const int n = tid & 3;
    const int mB = (tid >> 2) * 4;

    // ---- phase A (mode1): h_top strip = relu(P[n0:n0+4,:] @ Q0cur) ----
    if (P) {
        {
            const int r = tid >> 6;
            const int c = (tid & 63) * 4;
            *(float4*)&ps[r][c] = *(const float4*)(P + (size_t)(n0 + r) * F + c);
        }
        __syncthreads();
        float acc[4] = {0.f, 0.f, 0.f, 0.f};
#pragma unroll 4
        for (int k = 0; k < F; k++) {
            float qv = Q0cur[(size_t)k * F + tid];
            acc[0] += ps[0][k] * qv;
            acc[1] += ps[1][k] * qv;
            acc[2] += ps[2][k] * qv;
            acc[3] += ps[3][k] * qv;
        }
#pragma unroll
        for (int r = 0; r < 4; r++) hs[r][tid] = fmaxf(acc[r], 0.f);
        __syncthreads();
    }

    // ---- phase B: scores -> tanh, build zt strip + Q strip ----
    {
        const int wid = tid >> 5, lane = tid & 31;
        if (wid < 4) {
            float p = 0.f;
#pragma unroll
            for (int f = lane; f < F; f += 32) {
                float hv = P ? hs[wid][f] : embs[(size_t)(n0 + wid) * F + f];
                p += hv * scorer[f];
            }
#pragma unroll
            for (int o = 16; o > 0; o >>= 1) p += __shfl_xor_sync(0xffffffffu, p, o);
            if (lane == 0) tvalS[wid] = tanhf(p / g_sn[layer]);
        }
    }
    __syncthreads();
    {
        float4 q4 = *(const float4*)(Qin + (size_t)tid * F + n0);
        qs[tid][0] = q4.x; qs[tid][1] = q4.y; qs[tid][2] = q4.z; qs[tid][3] = q4.w;
#pragma unroll
        for (int r = 0; r < 4; r++) {
            float hv = P ? hs[r][tid] : embs[(size_t)(n0 + r) * F + tid];
            zts[tid][r] = hv * tvalS[r];
        }
    }
    __syncthreads();

    // ---- phase C: gates z, r, h ----
    float upd[4], whz[4];
    for (int gate = 0; gate < 3; gate++) {
        const float* W = (gate == 0) ? Wz : ((gate == 1) ? Wr : Wh);
        const float* U = (gate == 0) ? Uz : Ur;
        float acc[4] = {0.f, 0.f, 0.f, 0.f};
        for (int kt = 0; kt < 32; kt++) {
            {
                float4 w0 = *(const float4*)(W + (size_t)tid * F + kt * 8);
                float4 w1 = *(const float4*)(W + (size_t)tid * F + kt * 8 + 4);
                wt[0][tid] = w0.x; wt[1][tid] = w0.y; wt[2][tid] = w0.z; wt[3][tid] = w0.w;
                wt[4][tid] = w1.x; wt[5][tid] = w1.y; wt[6][tid] = w1.z; wt[7][tid] = w1.w;
                if (gate < 2) {
                    float4 u0 = *(const float4*)(U + (size_t)tid * F + kt * 8);
                    float4 u1 = *(const float4*)(U + (size_t)tid * F + kt * 8 + 4);
                    ut[0][tid] = u0.x; ut[1][tid] = u0.y; ut[2][tid] = u0.z; ut[3][tid] = u0.w;
                    ut[4][tid] = u1.x; ut[5][tid] = u1.y; ut[6][tid] = u1.z; ut[7][tid] = u1.w;
                }
            }
            __syncthreads();
            if (gate < 2) {
#pragma unroll
                for (int kk = 0; kk < 8; kk++) {
                    const int k = kt * 8 + kk;
                    float zv = zts[k][n];
                    float qv = qs[k][n];
                    float4 w = *(const float4*)&wt[kk][mB];
                    float4 u = *(const float4*)&ut[kk][mB];
                    acc[0] += w.x * zv + u.x * qv;
                    acc[1] += w.y * zv + u.y * qv;
                    acc[2] += w.z * zv + u.z * qv;
                    acc[3] += w.w * zv + u.w * qv;
                }
            } else {
#pragma unroll
                for (int kk = 0; kk < 8; kk++) {
                    const int k = kt * 8 + kk;
                    float zv = zts[k][n];
                    float4 w = *(const float4*)&wt[kk][mB];
                    acc[0] += w.x * zv; acc[1] += w.y * zv;
                    acc[2] += w.z * zv; acc[3] += w.w * zv;
                }
            }
            __syncthreads();
        }
        if (gate == 0) {
#pragma unroll
            for (int i = 0; i < 4; i++)
                upd[i] = 1.f / (1.f + expf(-(acc[i] + bz[(size_t)(mB + i) * F + n0 + n])));
        } else if (gate == 1) {
#pragma unroll
            for (int i = 0; i < 4; i++) {
                float r_ = 1.f / (1.f + expf(-(acc[i] + br[(size_t)(mB + i) * F + n0 + n])));
                rqs[mB + i][n] = r_ * qs[mB + i][n];
            }
        } else {
#pragma unroll
            for (int i = 0; i < 4; i++)
                whz[i] = acc[i] + bh[(size_t)(mB + i) * F + n0 + n];
        }
    }

    // ---- phase D: stage2  hcap = tanh(whz + Uh@(rst*Q)); Qn = (1-u)Q + u*hcap ----
    float acc2[4] = {0.f, 0.f, 0.f, 0.f};
    for (int kt = 0; kt < 32; kt++) {
        {
            float4 w0 = *(const float4*)(Uh + (size_t)tid * F + kt * 8);
            float4 w1 = *(const float4*)(Uh + (size_t)tid * F + kt * 8 + 4);
            wt[0][tid] = w0.x; wt[1][tid] = w0.y; wt[2][tid] = w0.z; wt[3][tid] = w0.w;
            wt[4][tid] = w1.x; wt[5][tid] = w1.y; wt[6][tid] = w1.z; wt[7][tid] = w1.w;
        }
        __syncthreads();
#pragma unroll
        for (int kk = 0; kk < 8; kk++) {
            const int k = kt * 8 + kk;
            float rv = rqs[k][n];
            float4 u = *(const float4*)&wt[kk][mB];
            acc2[0] += u.x * rv; acc2[1] += u.y * rv;
            acc2[2] += u.z * rv; acc2[3] += u.w * rv;
        }
        __syncthreads();
    }
#pragma unroll
    for (int i = 0; i < 4; i++) {
        float hc = tanhf(whz[i] + acc2[i]);
        float u_ = upd[i];
        float q_ = qs[mB + i][n];
        Qout[(size_t)(mB + i) * F + n0 + n] = (1.f - u_) * q_ + u_ * hc;
    }
}

// ---------------- generic SGEMM: C = [relu](A @ B), row-major ----------------
// block tile 128(M) x 64(N), K-tile 16, 256 threads, 8x4 per thread
__global__ void __launch_bounds__(256) sgemm_kernel(const float* __restrict__ A,
                                                    const float* __restrict__ B,
                                                    float* __restrict__ C,
                                                    int M, int N, int K, int do_relu) {
    __shared__ float As[16][128];
    __shared__ float Bs[16][64];
    const int bm = blockIdx.y * 128;
    const int bn = blockIdx.x * 64;
    const int tid = threadIdx.x;
    const int tx = tid & 15;
    const int ty = tid >> 4;

    float acc[8][4];
#pragma unroll
    for (int i = 0; i < 8; i++)
#pragma unroll
        for (int j = 0; j < 4; j++) acc[i][j] = 0.f;

    const int arow0 = tid >> 2;
    const int akk = (tid & 3) << 2;
    const int brow = tid >> 4;
    const int bnn = (tid & 15) << 2;

    for (int k0 = 0; k0 < K; k0 += 16) {
#pragma unroll
        for (int i = 0; i < 2; i++) {
            const int row = arow0 + i * 64;
            float4 v = *(const float4*)(A + (size_t)(bm + row) * K + (k0 + akk));
            As[akk + 0][row] = v.x;
            As[akk + 1][row] = v.y;
            As[akk + 2][row] = v.z;
            As[akk + 3][row] = v.w;
        }
        {
            float4 v = *(const float4*)(B + (size_t)(k0 + brow) * N + (bn + bnn));
            *(float4*)(&Bs[brow][bnn]) = v;
        }
        __syncthreads();
#pragma unroll
        for (int k = 0; k < 16; k++) {
            float4 a0 = *(const float4*)(&As[k][ty * 8]);
            float4 a1 = *(const float4*)(&As[k][ty * 8 + 4]);
            float4 bv = *(const float4*)(&Bs[k][tx * 4]);
            float a[8] = {a0.x, a0.y, a0.z, a0.w, a1.x, a1.y, a1.z, a1.w};
            float b[4] = {bv.x, bv.y, bv.z, bv.w};
#pragma unroll
            for (int i = 0; i < 8; i++)
#pragma unroll
                for (int j = 0; j < 4; j++) acc[i][j] += a[i] * b[j];
        }
        __syncthreads();
    }
#pragma unroll
    for (int i = 0; i < 8; i++) {
        float4 v;
        v.x = acc[i][0]; v.y = acc[i][1]; v.z = acc[i][2]; v.w = acc[i][3];
        if (do_relu) {
            v.x = fmaxf(v.x, 0.f); v.y = fmaxf(v.y, 0.f);
            v.z = fmaxf(v.z, 0.f); v.w = fmaxf(v.w, 0.f);
        }
        *(float4*)(C + (size_t)(bm + ty * 8 + i) * N + bn + tx * 4) = v;
    }
}

// ---------------- orchestration ----------------
extern "C" void kernel_launch(void* const* d_in, const int* in_sizes, int n_in,
                              void* d_out, int out_size) {
    const float* in[25];
    for (int i = 0; i < 25; i++) in[i] = (const float*)d_in[i];
    const float* A = in[0];
    const float* X = in[1];
    // 3: l0_scorer, 4..13: l0 Wz Uz bz Wr Ur br Wh Uh bh Q0
    // 14: l1_scorer, 15..24: l1 Wz Uz bz Wr Ur br Wh Uh bh Q0

    float *Qb, *Pb, *Y, *h1;
    cudaGetSymbolAddress((void**)&Qb, g_Q);
    cudaGetSymbolAddress((void**)&Pb, g_P);
    cudaGetSymbolAddress((void**)&Y, g_Y);
    cudaGetSymbolAddress((void**)&h1, g_h1);

    sn_kernel<<<2, 256>>>(in[3], in[14]);
    pbatch_kernel<<<dim3(4, 8, 7), 256>>>(A, X, Pb);

    for (int t = 0; t < TT; t++) {
        const float* embs0 = X + (size_t)t * NN * F;
        const float* q0in = (t == 0) ? in[13] : Qb + (size_t)(0 * 2 + ((t - 1) & 1)) * F * F;
        float* q0out = Qb + (size_t)(0 * 2 + (t & 1)) * F * F;
        const float* q1in = (t == 0) ? in[24] : Qb + (size_t)(2 + ((t - 1) & 1)) * F * F;
        float* q1out = Qb + (size_t)(2 + (t & 1)) * F * F;

        // layer 0 GRU (zt from X[t] rows 0..255)
        gru_kernel<<<64, 256>>>(embs0, nullptr, nullptr, in[3], 0,
                                in[4], in[5], in[6], in[7], in[8], in[9],
                                in[10], in[11], in[12], q0in, q0out);

        if (t < TT - 1) {
            // layer 1 GRU with fused h_top = relu(P[t] @ Q0_new)
            gru_kernel<<<64, 256>>>(nullptr, Pb + (size_t)t * F * F, q0out, in[14], 1,
                                    in[15], in[16], in[17], in[18], in[19], in[20],
                                    in[21], in[22], in[23], q1in, q1out);
        } else {
            const float* At = A + (size_t)t * NN * NN;
            // full h1 = relu(A7 @ (X7 @ Q0))
            sgemm_kernel<<<dim3(4, 32), 256>>>(embs0, q0out, Y, NN, F, F, 0);
            sgemm_kernel<<<dim3(4, 32), 256>>>(At, Y, h1, NN, F, NN, 1);
            // layer 1 GRU (zt from h1 rows 0..255)
            gru_kernel<<<64, 256>>>(h1, nullptr, nullptr, in[14], 1,
                                    in[15], in[16], in[17], in[18], in[19], in[20],
                                    in[21], in[22], in[23], q1in, q1out);
            // out = relu(A7 @ (h1 @ Q1))
            sgemm_kernel<<<dim3(4, 32), 256>>>(h1, q1out, Y, NN, F, F, 0);
            sgemm_kernel<<<dim3(4, 32), 256>>>(At, Y, (float*)d_out, NN, F, NN, 1);
        }
    }
}

// round 6
// speedup vs baseline: 2.5988x; 1.7876x over previous
#include <cuda_runtime.h>
#include <math.h>

#define F 256
#define NN 4096
#define TT 8

// ---------------- scratch (no allocations allowed) ----------------
__device__ float g_sn[2];
__device__ float g_Q[2 * 2 * F * F];   // [layer][pingpong][F*F]
__device__ float g_P[7 * F * F];       // P[t] = A[t][0:256,:] @ X[t]
__device__ float g_E[F * F];           // layer-1 h_top
__device__ float g_tv0[TT * F];        // layer-0 tanh(score) for all t
__device__ float g_tv[F];              // layer-1 tanh(score), current step
__device__ float g_upd[F * F];
__device__ float g_rq[F * F];
__device__ float g_whz[F * F];
__device__ float g_Y[NN * F];
__device__ float g_h1[NN * F];

// ---------------- scorer norms ----------------
__global__ void __launch_bounds__(256) sn_kernel(const float* __restrict__ s0,
                                                 const float* __restrict__ s1) {
    const float* s = (blockIdx.x == 0) ? s0 : s1;
    float p = s[threadIdx.x];
    p = p * p;
#pragma unroll
    for (int o = 16; o > 0; o >>= 1) p += __shfl_xor_sync(0xffffffffu, p, o);
    __shared__ float ws[8];
    if ((threadIdx.x & 31) == 0) ws[threadIdx.x >> 5] = p;
    __syncthreads();
    if (threadIdx.x == 0) {
        float sum = 0.f;
#pragma unroll
        for (int i = 0; i < 8; i++) sum += ws[i];
        g_sn[blockIdx.x] = sqrtf(sum);
    }
}

// ---------------- tval[row] = tanh((E[row,:] . scorer) / sn), rows 0..255 -----
// grid (32, nT): one warp per row; E_t = Ebase + t*tstride, out_t = out + t*F
__global__ void __launch_bounds__(256) tval_kernel(const float* __restrict__ Ebase,
                                                   size_t tstride,
                                                   const float* __restrict__ scorer,
                                                   int layer, float* __restrict__ out) {
    const float* E = Ebase + (size_t)blockIdx.y * tstride;
    const int wid = threadIdx.x >> 5, lane = threadIdx.x & 31;
    const int row = blockIdx.x * 8 + wid;
    float p = 0.f;
#pragma unroll
    for (int c = lane; c < F; c += 32) p += E[(size_t)row * F + c] * scorer[c];
#pragma unroll
    for (int o = 16; o > 0; o >>= 1) p += __shfl_xor_sync(0xffffffffu, p, o);
    if (lane == 0) out[(size_t)blockIdx.y * F + row] = tanhf(p / g_sn[layer]);
}

// ---------------- prep1: h_top = relu(P @ Q0), write E + tval (layer 1) ------
// grid 64 blocks, each owns 4 rows; 256 threads = columns
__global__ void __launch_bounds__(256) prep1_kernel(const float* __restrict__ P,
                                                    const float* __restrict__ Q0,
                                                    const float* __restrict__ scorer,
                                                    float* __restrict__ Eout,
                                                    float* __restrict__ tvout) {
    __shared__ float ps[4][F];
    __shared__ float red[4][8];
    const int tid = threadIdx.x;
    const int r0 = blockIdx.x * 4;
#pragma unroll
    for (int r = 0; r < 4; r++) ps[r][tid] = P[(size_t)(r0 + r) * F + tid];
    __syncthreads();
    float a0 = 0.f, a1 = 0.f, a2 = 0.f, a3 = 0.f;
#pragma unroll 8
    for (int k = 0; k < F; k++) {
        float qv = Q0[(size_t)k * F + tid];
        a0 += ps[0][k] * qv; a1 += ps[1][k] * qv;
        a2 += ps[2][k] * qv; a3 += ps[3][k] * qv;
    }
    a0 = fmaxf(a0, 0.f); a1 = fmaxf(a1, 0.f);
    a2 = fmaxf(a2, 0.f); a3 = fmaxf(a3, 0.f);
    Eout[(size_t)(r0 + 0) * F + tid] = a0;
    Eout[(size_t)(r0 + 1) * F + tid] = a1;
    Eout[(size_t)(r0 + 2) * F + tid] = a2;
    Eout[(size_t)(r0 + 3) * F + tid] = a3;
    const float sc = scorer[tid];
    float p[4] = {a0 * sc, a1 * sc, a2 * sc, a3 * sc};
    const int wid = tid >> 5, lane = tid & 31;
#pragma unroll
    for (int r = 0; r < 4; r++) {
#pragma unroll
        for (int o = 16; o > 0; o >>= 1) p[r] += __shfl_xor_sync(0xffffffffu, p[r], o);
        if (lane == 0) red[r][wid] = p[r];
    }
    __syncthreads();
    if (tid < 4) {
        float s = 0.f;
#pragma unroll
        for (int i = 0; i < 8; i++) s += red[tid][i];
        tvout[r0 + tid] = tanhf(s / g_sn[1]);
    }
}

// ---------------- GRU stage 1 -------------------------------------------------
// S_g[m,n] = tv[n]*(W_g @ E^T)[m,n] + (U_g @ Q)[m,n] + b_g[m,n]   (gate h: no U)
// gate0 -> upd = sigmoid(S); gate1 -> rq = sigmoid(S)*Q; gate2 -> whz = S
// grid (8 m-tiles, 8 n-tiles, 3 gates), 256 threads, 32x32 tiles, 2x2/thread
__global__ void __launch_bounds__(256) stage1_kernel(
    const float* __restrict__ Wz, const float* __restrict__ Uz, const float* __restrict__ bz,
    const float* __restrict__ Wr, const float* __restrict__ Ur, const float* __restrict__ br,
    const float* __restrict__ Wh, const float* __restrict__ bh,
    const float* __restrict__ E, const float* __restrict__ tv,
    const float* __restrict__ Q,
    float* __restrict__ upd, float* __restrict__ rq, float* __restrict__ whz) {
    const int gate = blockIdx.z;
    const float* W = (gate == 0) ? Wz : ((gate == 1) ? Wr : Wh);
    const float* U = (gate == 0) ? Uz : Ur;  // unused for gate 2
    const float* bias = (gate == 0) ? bz : ((gate == 1) ? br : bh);

    __shared__ float Ws[32][17];
    __shared__ float Es[32][17];
    __shared__ float Us[32][17];
    __shared__ float Qs[16][32];

    const int bm = blockIdx.x * 32;
    const int bn = blockIdx.y * 32;
    const int tid = threadIdx.x;
    const int tx = tid & 15, ty = tid >> 4;
    const int m0 = ty * 2, n0 = tx * 2;

    const int lrow = tid >> 3;           // 0..31
    const int lkk = (tid & 7) * 2;       // 0..14
    const int qk = tid >> 4;             // 0..15
    const int qn = (tid & 15) * 2;       // 0..30

    float nt00 = 0.f, nt01 = 0.f, nt10 = 0.f, nt11 = 0.f;
    float nn00 = 0.f, nn01 = 0.f, nn10 = 0.f, nn11 = 0.f;

    for (int k0 = 0; k0 < F; k0 += 16) {
        {
            float2 w = *(const float2*)(W + (size_t)(bm + lrow) * F + k0 + lkk);
            Ws[lrow][lkk] = w.x; Ws[lrow][lkk + 1] = w.y;
            float2 e = *(const float2*)(E + (size_t)(bn + lrow) * F + k0 + lkk);
            Es[lrow][lkk] = e.x; Es[lrow][lkk + 1] = e.y;
        }
        if (gate < 2) {
            float2 u = *(const float2*)(U + (size_t)(bm + lrow) * F + k0 + lkk);
            Us[lrow][lkk] = u.x; Us[lrow][lkk + 1] = u.y;
            float2 q = *(const float2*)(Q + (size_t)(k0 + qk) * F + bn + qn);
            Qs[qk][qn] = q.x; Qs[qk][qn + 1] = q.y;
        }
        __syncthreads();
        if (gate < 2) {
#pragma unroll
            for (int k = 0; k < 16; k++) {
                float w0 = Ws[m0][k], w1 = Ws[m0 + 1][k];
                float e0 = Es[n0][k], e1 = Es[n0 + 1][k];
                float u0 = Us[m0][k], u1 = Us[m0 + 1][k];
                float q0 = Qs[k][n0], q1 = Qs[k][n0 + 1];
                nt00 += w0 * e0; nt01 += w0 * e1;
                nt10 += w1 * e0; nt11 += w1 * e1;
                nn00 += u0 * q0; nn01 += u0 * q1;
                nn10 += u1 * q0; nn11 += u1 * q1;
            }
        } else {
#pragma unroll
            for (int k = 0; k < 16; k++) {
                float w0 = Ws[m0][k], w1 = Ws[m0 + 1][k];
                float e0 = Es[n0][k], e1 = Es[n0 + 1][k];
                nt00 += w0 * e0; nt01 += w0 * e1;
                nt10 += w1 * e0; nt11 += w1 * e1;
            }
        }
        __syncthreads();
    }

    const float tv0 = tv[bn + n0], tv1 = tv[bn + n0 + 1];
    float S[2][2];
    S[0][0] = tv0 * nt00 + nn00; S[0][1] = tv1 * nt01 + nn01;
    S[1][0] = tv0 * nt10 + nn10; S[1][1] = tv1 * nt11 + nn11;
#pragma unroll
    for (int i = 0; i < 2; i++)
#pragma unroll
        for (int j = 0; j < 2; j++) {
            const size_t idx = (size_t)(bm + m0 + i) * F + bn + n0 + j;
            float v = S[i][j] + bias[idx];
            if (gate == 0) {
                upd[idx] = 1.f / (1.f + expf(-v));
            } else if (gate == 1) {
                rq[idx] = (1.f / (1.f + expf(-v))) * Q[idx];
            } else {
                whz[idx] = v;
            }
        }
}

// ---------------- GRU stage 2: Qn = (1-u)Q + u*tanh(whz + Uh@rq) --------------
// grid (8,8), 256 threads, 32x32 tiles, 2x2/thread
__global__ void __launch_bounds__(256) stage2_kernel(
    const float* __restrict__ Uh, const float* __restrict__ Q,
    const float* __restrict__ rq, const float* __restrict__ upd,
    const float* __restrict__ whz, float* __restrict__ Qout) {
    __shared__ float Us[32][17];
    __shared__ float Rs[16][32];
    const int bm = blockIdx.x * 32;
    const int bn = blockIdx.y * 32;
    const int tid = threadIdx.x;
    const int tx = tid & 15, ty = tid >> 4;
    const int m0 = ty * 2, n0 = tx * 2;
    const int lrow = tid >> 3;
    const int lkk = (tid & 7) * 2;
    const int qk = tid >> 4;
    const int qn = (tid & 15) * 2;

    float c00 = 0.f, c01 = 0.f, c10 = 0.f, c11 = 0.f;
    for (int k0 = 0; k0 < F; k0 += 16) {
        {
            float2 u = *(const float2*)(Uh + (size_t)(bm + lrow) * F + k0 + lkk);
            Us[lrow][lkk] = u.x; Us[lrow][lkk + 1] = u.y;
            float2 r = *(const float2*)(rq + (size_t)(k0 + qk) * F + bn + qn);
            Rs[qk][qn] = r.x; Rs[qk][qn + 1] = r.y;
        }
        __syncthreads();
#pragma unroll
        for (int k = 0; k < 16; k++) {
            float u0 = Us[m0][k], u1 = Us[m0 + 1][k];
            float r0 = Rs[k][n0], r1 = Rs[k][n0 + 1];
            c00 += u0 * r0; c01 += u0 * r1;
            c10 += u1 * r0; c11 += u1 * r1;
        }
        __syncthreads();
    }
    float c[2][2] = {{c00, c01}, {c10, c11}};
#pragma unroll
    for (int i = 0; i < 2; i++)
#pragma unroll
        for (int j = 0; j < 2; j++) {
            const size_t idx = (size_t)(bm + m0 + i) * F + bn + n0 + j;
            float hc = tanhf(c[i][j] + whz[idx]);
            float u_ = upd[idx];
            Qout[idx] = (1.f - u_) * Q[idx] + u_ * hc;
        }
}

// ---------------- batched P[t] = A[t][0:256,:] @ X[t]  (t = 0..6) ----------------
__global__ void __launch_bounds__(256) pbatch_kernel(const float* __restrict__ A,
                                                     const float* __restrict__ X,
                                                     float* __restrict__ Pout) {
    const int t = blockIdx.z;
    const float* Ap = A + (size_t)t * NN * NN;
    const float* Bp = X + (size_t)t * NN * F;
    float* Cp = Pout + (size_t)t * F * F;

    __shared__ float As2[32][16];
    __shared__ float Bs[16][64];
    const int bm = blockIdx.y * 32;
    const int bn = blockIdx.x * 64;
    const int tid = threadIdx.x;
    const int tx = tid & 15;
    const int ty = tid >> 4;

    float acc[2][4];
#pragma unroll
    for (int i = 0; i < 2; i++)
#pragma unroll
        for (int j = 0; j < 4; j++) acc[i][j] = 0.f;

    const int arow = tid >> 3;
    const int akk = (tid & 7) * 2;
    const int brow = tid >> 4;
    const int bcol = (tid & 15) * 4;

    for (int k0 = 0; k0 < NN; k0 += 16) {
        float2 av = *(const float2*)(Ap + (size_t)(bm + arow) * NN + k0 + akk);
        As2[arow][akk] = av.x;
        As2[arow][akk + 1] = av.y;
        *(float4*)&Bs[brow][bcol] = *(const float4*)(Bp + (size_t)(k0 + brow) * F + bn + bcol);
        __syncthreads();
#pragma unroll
        for (int kk = 0; kk < 16; kk++) {
            float a0 = As2[ty * 2][kk];
            float a1 = As2[ty * 2 + 1][kk];
            float4 b = *(const float4*)&Bs[kk][tx * 4];
            acc[0][0] += a0 * b.x; acc[0][1] += a0 * b.y;
            acc[0][2] += a0 * b.z; acc[0][3] += a0 * b.w;
            acc[1][0] += a1 * b.x; acc[1][1] += a1 * b.y;
            acc[1][2] += a1 * b.z; acc[1][3] += a1 * b.w;
        }
        __syncthreads();
    }
#pragma unroll
    for (int i = 0; i < 2; i++) {
        float4 v;
        v.x = acc[i][0]; v.y = acc[i][1]; v.z = acc[i][2]; v.w = acc[i][3];
        *(float4*)(Cp + (size_t)(bm + ty * 2 + i) * F + bn + tx * 4) = v;
    }
}

// ---------------- generic SGEMM: C = [relu](A @ B), row-major ----------------
__global__ void __launch_bounds__(256) sgemm_kernel(const float* __restrict__ A,
                                                    const float* __restrict__ B,
                                                    float* __restrict__ C,
                                                    int M, int N, int K, int do_relu) {
    __shared__ float As[16][128];
    __shared__ float Bs[16][64];
    const int bm = blockIdx.y * 128;
    const int bn = blockIdx.x * 64;
    const int tid = threadIdx.x;
    const int tx = tid & 15;
    const int ty = tid >> 4;

    float acc[8][4];
#pragma unroll
    for (int i = 0; i < 8; i++)
#pragma unroll
        for (int j = 0; j < 4; j++) acc[i][j] = 0.f;

    const int arow0 = tid >> 2;
    const int akk = (tid & 3) << 2;
    const int brow = tid >> 4;
    const int bnn = (tid & 15) << 2;

    for (int k0 = 0; k0 < K; k0 += 16) {
#pragma unroll
        for (int i = 0; i < 2; i++) {
            const int row = arow0 + i * 64;
            float4 v = *(const float4*)(A + (size_t)(bm + row) * K + (k0 + akk));
            As[akk + 0][row] = v.x;
            As[akk + 1][row] = v.y;
            As[akk + 2][row] = v.z;
            As[akk + 3][row] = v.w;
        }
        {
            float4 v = *(const float4*)(B + (size_t)(k0 + brow) * N + (bn + bnn));
            *(float4*)(&Bs[brow][bnn]) = v;
        }
        __syncthreads();
#pragma unroll
        for (int k = 0; k < 16; k++) {
            float4 a0 = *(const float4*)(&As[k][ty * 8]);
            float4 a1 = *(const float4*)(&As[k][ty * 8 + 4]);
            float4 bv = *(const float4*)(&Bs[k][tx * 4]);
            float a[8] = {a0.x, a0.y, a0.z, a0.w, a1.x, a1.y, a1.z, a1.w};
            float b[4] = {bv.x, bv.y, bv.z, bv.w};
#pragma unroll
            for (int i = 0; i < 8; i++)
#pragma unroll
                for (int j = 0; j < 4; j++) acc[i][j] += a[i] * b[j];
        }
        __syncthreads();
    }
#pragma unroll
    for (int i = 0; i < 8; i++) {
        float4 v;
        v.x = acc[i][0]; v.y = acc[i][1]; v.z = acc[i][2]; v.w = acc[i][3];
        if (do_relu) {
            v.x = fmaxf(v.x, 0.f); v.y = fmaxf(v.y, 0.f);
            v.z = fmaxf(v.z, 0.f); v.w = fmaxf(v.w, 0.f);
        }
        *(float4*)(C + (size_t)(bm + ty * 8 + i) * N + bn + tx * 4) = v;
    }
}

// ---------------- orchestration ----------------
extern "C" void kernel_launch(void* const* d_in, const int* in_sizes, int n_in,
                              void* d_out, int out_size) {
    const float* in[25];
    for (int i = 0; i < 25; i++) in[i] = (const float*)d_in[i];
    const float* A = in[0];
    const float* X = in[1];
    // 3: l0_scorer, 4..13: l0 Wz Uz bz Wr Ur br Wh Uh bh Q0
    // 14: l1_scorer, 15..24: l1 Wz Uz bz Wr Ur br Wh Uh bh Q0

    float *Qb, *Pb, *Eb, *tv0, *tv1, *updb, *rqb, *whzb, *Y, *h1;
    cudaGetSymbolAddress((void**)&Qb, g_Q);
    cudaGetSymbolAddress((void**)&Pb, g_P);
    cudaGetSymbolAddress((void**)&Eb, g_E);
    cudaGetSymbolAddress((void**)&tv0, g_tv0);
    cudaGetSymbolAddress((void**)&tv1, g_tv);
    cudaGetSymbolAddress((void**)&updb, g_upd);
    cudaGetSymbolAddress((void**)&rqb, g_rq);
    cudaGetSymbolAddress((void**)&whzb, g_whz);
    cudaGetSymbolAddress((void**)&Y, g_Y);
    cudaGetSymbolAddress((void**)&h1, g_h1);

    sn_kernel<<<2, 256>>>(in[3], in[14]);
    pbatch_kernel<<<dim3(4, 8, 7), 256>>>(A, X, Pb);
    // all layer-0 tvals in one batched launch
    tval_kernel<<<dim3(32, TT), 256>>>(X, (size_t)NN * F, in[3], 0, tv0);

    for (int t = 0; t < TT; t++) {
        const float* embs0 = X + (size_t)t * NN * F;
        const float* q0in = (t == 0) ? in[13] : Qb + (size_t)(0 * 2 + ((t - 1) & 1)) * F * F;
        float* q0out = Qb + (size_t)(0 * 2 + (t & 1)) * F * F;
        const float* q1in = (t == 0) ? in[24] : Qb + (size_t)(2 + ((t - 1) & 1)) * F * F;
        float* q1out = Qb + (size_t)(2 + (t & 1)) * F * F;

        // ---- layer 0 GRU ----
        stage1_kernel<<<dim3(8, 8, 3), 256>>>(in[4], in[5], in[6], in[7], in[8], in[9],
                                              in[10], in[12], embs0, tv0 + t * F, q0in,
                                              updb, rqb, whzb);
        stage2_kernel<<<dim3(8, 8), 256>>>(in[11], q0in, rqb, updb, whzb, q0out);

        if (t < TT - 1) {
            // ---- layer 1: h_top + tval, then GRU ----
            prep1_kernel<<<64, 256>>>(Pb + (size_t)t * F * F, q0out, in[14], Eb, tv1);
            stage1_kernel<<<dim3(8, 8, 3), 256>>>(in[15], in[16], in[17], in[18], in[19],
                                                  in[20], in[21], in[23], Eb, tv1, q1in,
                                                  updb, rqb, whzb);
            stage2_kernel<<<dim3(8, 8), 256>>>(in[22], q1in, rqb, updb, whzb, q1out);
        } else {
            const float* At = A + (size_t)t * NN * NN;
            // full h1 = relu(A7 @ (X7 @ Q0))
            sgemm_kernel<<<dim3(4, 32), 256>>>(embs0, q0out, Y, NN, F, F, 0);
            sgemm_kernel<<<dim3(4, 32), 256>>>(At, Y, h1, NN, F, NN, 1);
            // layer-1 GRU from h1
            tval_kernel<<<dim3(32, 1), 256>>>(h1, 0, in[14], 1, tv1);
            stage1_kernel<<<dim3(8, 8, 3), 256>>>(in[15], in[16], in[17], in[18], in[19],
                                                  in[20], in[21], in[23], h1, tv1, q1in,
                                                  updb, rqb, whzb);
            stage2_kernel<<<dim3(8, 8), 256>>>(in[22], q1in, rqb, updb, whzb, q1out);
            // out = relu(A7 @ (h1 @ Q1))
            sgemm_kernel<<<dim3(4, 32), 256>>>(h1, q1out, Y, NN, F, F, 0);
            sgemm_kernel<<<dim3(4, 32), 256>>>(At, Y, (float*)d_out, NN, F, NN, 1);
        }
    }
}

// round 8
// speedup vs baseline: 3.3132x; 1.2749x over previous
#include <cuda_runtime.h>
#include <math.h>
#include <stdint.h>

#define F 256
#define NN 4096
#define TT 8

// ---------------- scratch (no allocations allowed) ----------------
__device__ float g_sn[2];
__device__ float g_Q[2 * 2 * F * F];   // [layer][pingpong][F*F]
__device__ float g_P[7 * F * F];       // P[t] = A[t][0:256,:] @ X[t]
__device__ float g_E[F * F];           // layer-1 h_top
__device__ float g_tv0[TT * F];        // layer-0 tanh(score) for all t
__device__ float g_tv[F];              // layer-1 tanh(score), current step
__device__ float g_upd[F * F];
__device__ float g_rq[F * F];
__device__ float g_whz[F * F];
__device__ float g_Yt[F * NN];         // transposed Y: [256, 4096] k-major B operand
__device__ float g_h1[NN * F];
__device__ float g_Xt[7 * F * NN];     // transposed X per t (B operand for P GEMMs)

// =================== tf32 split helpers ===================
__device__ __forceinline__ void split2(float v, uint32_t& hi, uint32_t& lo) {
    uint32_t u = __float_as_uint(v) & 0xffffe000u;
    hi = u;
    lo = __float_as_uint(v - __uint_as_float(u));
}

__device__ __forceinline__ void mma_tf32(float* d, const uint32_t* a, const uint32_t* b) {
    asm volatile(
        "mma.sync.aligned.m16n8k8.row.col.f32.tf32.tf32.f32 "
        "{%0,%1,%2,%3}, {%4,%5,%6,%7}, {%8,%9}, {%0,%1,%2,%3};\n"
        : "+f"(d[0]), "+f"(d[1]), "+f"(d[2]), "+f"(d[3])
        : "r"(a[0]), "r"(a[1]), "r"(a[2]), "r"(a[3]), "r"(b[0]), "r"(b[1]));
}

// ============ tf32 3x-split GEMM: C[.,256] = [relu](A[M,K] @ Bt[256,K]^T) =====
// CTA tile M=128, N=64, kc=16; 8 warps (4m x 2n), warp tile 32x32.
// Batched over blockIdx.z via byte strides. lda = ldb = K, ldc = 256.
__global__ void __launch_bounds__(256) tf32_gemm_kernel(
    const float* __restrict__ A, size_t strideA,
    const float* __restrict__ Bt, size_t strideB,
    float* __restrict__ C, size_t strideC,
    int K, int do_relu) {
    __shared__ float As[2][128][20];
    __shared__ float Bs[2][64][20];

    const float* Ap = A + strideA * blockIdx.z;
    const float* Bp = Bt + strideB * blockIdx.z;
    float* Cp = C + strideC * blockIdx.z;

    const int bm = blockIdx.y * 128;
    const int bn = blockIdx.x * 64;
    const int tid = threadIdx.x;
    const int wid = tid >> 5, lane = tid & 31;
    const int wm = (wid & 3) * 32;
    const int wn = (wid >> 2) * 32;
    const int gid = lane >> 2, tig = lane & 3;

    // tile-load indexing
    const int ar = tid >> 1;        // 0..127
    const int ak = (tid & 1) * 8;   // 0 or 8
    const int br = tid >> 2;        // 0..63
    const int bk = (tid & 3) * 4;   // 0,4,8,12

    float acc[2][4][4];
#pragma unroll
    for (int i = 0; i < 2; i++)
#pragma unroll
        for (int j = 0; j < 4; j++)
#pragma unroll
            for (int r = 0; r < 4; r++) acc[i][j][r] = 0.f;

    const int ntiles = K >> 4;

    float4 a0v = *(const float4*)(Ap + (size_t)(bm + ar) * K + ak);
    float4 a1v = *(const float4*)(Ap + (size_t)(bm + ar) * K + ak + 4);
    float4 bv = *(const float4*)(Bp + (size_t)(bn + br) * K + bk);
    *(float4*)&As[0][ar][ak] = a0v;
    *(float4*)&As[0][ar][ak + 4] = a1v;
    *(float4*)&Bs[0][br][bk] = bv;
    __syncthreads();

    for (int tile = 0; tile < ntiles; tile++) {
        const int buf = tile & 1;
        if (tile + 1 < ntiles) {
            const int k0 = (tile + 1) << 4;
            a0v = *(const float4*)(Ap + (size_t)(bm + ar) * K + k0 + ak);
            a1v = *(const float4*)(Ap + (size_t)(bm + ar) * K + k0 + ak + 4);
            bv = *(const float4*)(Bp + (size_t)(bn + br) * K + k0 + bk);
        }
#pragma unroll
        for (int ks = 0; ks < 2; ks++) {
            const int kb = ks * 8;
            uint32_t ahi[2][4], alo[2][4];
#pragma unroll
            for (int mf = 0; mf < 2; mf++) {
                const int r = wm + mf * 16 + gid;
                split2(As[buf][r][kb + tig], ahi[mf][0], alo[mf][0]);
                split2(As[buf][r + 8][kb + tig], ahi[mf][1], alo[mf][1]);
                split2(As[buf][r][kb + tig + 4], ahi[mf][2], alo[mf][2]);
                split2(As[buf][r + 8][kb + tig + 4], ahi[mf][3], alo[mf][3]);
            }
            uint32_t bhi[4][2], blo[4][2];
#pragma unroll
            for (int nf = 0; nf < 4; nf++) {
                const int n = wn + nf * 8 + gid;
                split2(Bs[buf][n][kb + tig], bhi[nf][0], blo[nf][0]);
                split2(Bs[buf][n][kb + tig + 4], bhi[nf][1], blo[nf][1]);
            }
#pragma unroll
            for (int mf = 0; mf < 2; mf++)
#pragma unroll
                for (int nf = 0; nf < 4; nf++) {
                    mma_tf32(acc[mf][nf], ahi[mf], bhi[nf]);
                    mma_tf32(acc[mf][nf], ahi[mf], blo[nf]);
                    mma_tf32(acc[mf][nf], alo[mf], bhi[nf]);
                }
        }
        __syncthreads();
        if (tile + 1 < ntiles) {
            const int nb = (tile + 1) & 1;
            *(float4*)&As[nb][ar][ak] = a0v;
            *(float4*)&As[nb][ar][ak + 4] = a1v;
            *(float4*)&Bs[nb][br][bk] = bv;
            __syncthreads();
        }
    }

#pragma unroll
    for (int mf = 0; mf < 2; mf++)
#pragma unroll
        for (int nf = 0; nf < 4; nf++) {
            const int row = bm + wm + mf * 16 + gid;
            const int col = bn + wn + nf * 8 + tig * 2;
            float v0 = acc[mf][nf][0], v1 = acc[mf][nf][1];
            float v2 = acc[mf][nf][2], v3 = acc[mf][nf][3];
            if (do_relu) {
                v0 = fmaxf(v0, 0.f); v1 = fmaxf(v1, 0.f);
                v2 = fmaxf(v2, 0.f); v3 = fmaxf(v3, 0.f);
            }
            Cp[(size_t)row * F + col] = v0;
            Cp[(size_t)row * F + col + 1] = v1;
            Cp[(size_t)(row + 8) * F + col] = v2;
            Cp[(size_t)(row + 8) * F + col + 1] = v3;
        }
}

// ---------------- Xt[t][f][n] = X[t][n][f]  (grid: (128, 8, 7), block 256) ----
__global__ void __launch_bounds__(256) transpose_kernel(const float* __restrict__ X,
                                                        float* __restrict__ Xt) {
    __shared__ float ts[32][33];
    const int t = blockIdx.z;
    const int nb = blockIdx.x * 32;
    const int fb = blockIdx.y * 32;
    const int tx = threadIdx.x & 31, ty = threadIdx.x >> 5;
    const float* src = X + (size_t)t * NN * F;
    float* dst = Xt + (size_t)t * F * NN;
#pragma unroll
    for (int j = 0; j < 32; j += 8)
        ts[ty + j][tx] = src[(size_t)(nb + ty + j) * F + fb + tx];
    __syncthreads();
#pragma unroll
    for (int j = 0; j < 32; j += 8)
        dst[(size_t)(fb + ty + j) * NN + nb + tx] = ts[tx][ty + j];
}

// ---------------- scorer norms ----------------
__global__ void __launch_bounds__(256) sn_kernel(const float* __restrict__ s0,
                                                 const float* __restrict__ s1) {
    const float* s = (blockIdx.x == 0) ? s0 : s1;
    float p = s[threadIdx.x];
    p = p * p;
#pragma unroll
    for (int o = 16; o > 0; o >>= 1) p += __shfl_xor_sync(0xffffffffu, p, o);
    __shared__ float ws[8];
    if ((threadIdx.x & 31) == 0) ws[threadIdx.x >> 5] = p;
    __syncthreads();
    if (threadIdx.x == 0) {
        float sum = 0.f;
#pragma unroll
        for (int i = 0; i < 8; i++) sum += ws[i];
        g_sn[blockIdx.x] = sqrtf(sum);
    }
}

// ---------------- tval[row] = tanh((E[row,:] . scorer) / sn), rows 0..255 -----
__global__ void __launch_bounds__(256) tval_kernel(const float* __restrict__ Ebase,
                                                   size_t tstride,
                                                   const float* __restrict__ scorer,
                                                   int layer, float* __restrict__ out) {
    const float* E = Ebase + (size_t)blockIdx.y * tstride;
    const int wid = threadIdx.x >> 5, lane = threadIdx.x & 31;
    const int row = blockIdx.x * 8 + wid;
    float p = 0.f;
#pragma unroll
    for (int c = lane; c < F; c += 32) p += E[(size_t)row * F + c] * scorer[c];
#pragma unroll
    for (int o = 16; o > 0; o >>= 1) p += __shfl_xor_sync(0xffffffffu, p, o);
    if (lane == 0) out[(size_t)blockIdx.y * F + row] = tanhf(p / g_sn[layer]);
}

// ---------------- prep1: h_top = relu(P @ Q0), write E + tval (layer 1) ------
__global__ void __launch_bounds__(256) prep1_kernel(const float* __restrict__ P,
                                                    const float* __restrict__ Q0,
                                                    const float* __restrict__ scorer,
                                                    float* __restrict__ Eout,
                                                    float* __restrict__ tvout) {
    __shared__ float ps[4][F];
    __shared__ float red[4][8];
    const int tid = threadIdx.x;
    const int r0 = blockIdx.x * 4;
#pragma unroll
    for (int r = 0; r < 4; r++) ps[r][tid] = P[(size_t)(r0 + r) * F + tid];
    __syncthreads();
    float a0 = 0.f, a1 = 0.f, a2 = 0.f, a3 = 0.f;
#pragma unroll 8
    for (int k = 0; k < F; k++) {
        float qv = Q0[(size_t)k * F + tid];
        a0 += ps[0][k] * qv; a1 += ps[1][k] * qv;
        a2 += ps[2][k] * qv; a3 += ps[3][k] * qv;
    }
    a0 = fmaxf(a0, 0.f); a1 = fmaxf(a1, 0.f);
    a2 = fmaxf(a2, 0.f); a3 = fmaxf(a3, 0.f);
    Eout[(size_t)(r0 + 0) * F + tid] = a0;
    Eout[(size_t)(r0 + 1) * F + tid] = a1;
    Eout[(size_t)(r0 + 2) * F + tid] = a2;
    Eout[(size_t)(r0 + 3) * F + tid] = a3;
    const float sc = scorer[tid];
    float p[4] = {a0 * sc, a1 * sc, a2 * sc, a3 * sc};
    const int wid = tid >> 5, lane = tid & 31;
#pragma unroll
    for (int r = 0; r < 4; r++) {
#pragma unroll
        for (int o = 16; o > 0; o >>= 1) p[r] += __shfl_xor_sync(0xffffffffu, p[r], o);
        if (lane == 0) red[r][wid] = p[r];
    }
    __syncthreads();
    if (tid < 4) {
        float s = 0.f;
#pragma unroll
        for (int i = 0; i < 8; i++) s += red[tid][i];
        tvout[r0 + tid] = tanhf(s / g_sn[1]);
    }
}

// ---------------- GRU stage 1 -------------------------------------------------
__global__ void __launch_bounds__(256) stage1_kernel(
    const float* __restrict__ Wz, const float* __restrict__ Uz, const float* __restrict__ bz,
    const float* __restrict__ Wr, const float* __restrict__ Ur, const float* __restrict__ br,
    const float* __restrict__ Wh, const float* __restrict__ bh,
    const float* __restrict__ E, const float* __restrict__ tv,
    const float* __restrict__ Q,
    float* __restrict__ upd, float* __restrict__ rq, float* __restrict__ whz) {
    const int gate = blockIdx.z;
    const float* W = (gate == 0) ? Wz : ((gate == 1) ? Wr : Wh);
    const float* U = (gate == 0) ? Uz : Ur;
    const float* bias = (gate == 0) ? bz : ((gate == 1) ? br : bh);

    __shared__ float Ws[32][17];
    __shared__ float Es[32][17];
    __shared__ float Us[32][17];
    __shared__ float Qs[16][32];

    const int bm = blockIdx.x * 32;
    const int bn = blockIdx.y * 32;
    const int tid = threadIdx.x;
    const int tx = tid & 15, ty = tid >> 4;
    const int m0 = ty * 2, n0 = tx * 2;

    const int lrow = tid >> 3;
    const int lkk = (tid & 7) * 2;
    const int qk = tid >> 4;
    const int qn = (tid & 15) * 2;

    float nt00 = 0.f, nt01 = 0.f, nt10 = 0.f, nt11 = 0.f;
    float nn00 = 0.f, nn01 = 0.f, nn10 = 0.f, nn11 = 0.f;

    for (int k0 = 0; k0 < F; k0 += 16) {
        {
            float2 w = *(const float2*)(W + (size_t)(bm + lrow) * F + k0 + lkk);
            Ws[lrow][lkk] = w.x; Ws[lrow][lkk + 1] = w.y;
            float2 e = *(const float2*)(E + (size_t)(bn + lrow) * F + k0 + lkk);
            Es[lrow][lkk] = e.x; Es[lrow][lkk + 1] = e.y;
        }
        if (gate < 2) {
            float2 u = *(const float2*)(U + (size_t)(bm + lrow) * F + k0 + lkk);
            Us[lrow][lkk] = u.x; Us[lrow][lkk + 1] = u.y;
            float2 q = *(const float2*)(Q + (size_t)(k0 + qk) * F + bn + qn);
            Qs[qk][qn] = q.x; Qs[qk][qn + 1] = q.y;
        }
        __syncthreads();
        if (gate < 2) {
#pragma unroll
            for (int k = 0; k < 16; k++) {
                float w0 = Ws[m0][k], w1 = Ws[m0 + 1][k];
                float e0 = Es[n0][k], e1 = Es[n0 + 1][k];
                float u0 = Us[m0][k], u1 = Us[m0 + 1][k];
                float q0 = Qs[k][n0], q1 = Qs[k][n0 + 1];
                nt00 += w0 * e0; nt01 += w0 * e1;
                nt10 += w1 * e0; nt11 += w1 * e1;
                nn00 += u0 * q0; nn01 += u0 * q1;
                nn10 += u1 * q0; nn11 += u1 * q1;
            }
        } else {
#pragma unroll
            for (int k = 0; k < 16; k++) {
                float w0 = Ws[m0][k], w1 = Ws[m0 + 1][k];
                float e0 = Es[n0][k], e1 = Es[n0 + 1][k];
                nt00 += w0 * e0; nt01 += w0 * e1;
                nt10 += w1 * e0; nt11 += w1 * e1;
            }
        }
        __syncthreads();
    }

    const float tv0 = tv[bn + n0], tv1 = tv[bn + n0 + 1];
    float S[2][2];
    S[0][0] = tv0 * nt00 + nn00; S[0][1] = tv1 * nt01 + nn01;
    S[1][0] = tv0 * nt10 + nn10; S[1][1] = tv1 * nt11 + nn11;
#pragma unroll
    for (int i = 0; i < 2; i++)
#pragma unroll
        for (int j = 0; j < 2; j++) {
            const size_t idx = (size_t)(bm + m0 + i) * F + bn + n0 + j;
            float v = S[i][j] + bias[idx];
            if (gate == 0) {
                upd[idx] = 1.f / (1.f + expf(-v));
            } else if (gate == 1) {
                rq[idx] = (1.f / (1.f + expf(-v))) * Q[idx];
            } else {
                whz[idx] = v;
            }
        }
}

// ---------------- GRU stage 2: Qn = (1-u)Q + u*tanh(whz + Uh@rq) --------------
__global__ void __launch_bounds__(256) stage2_kernel(
    const float* __restrict__ Uh, const float* __restrict__ Q,
    const float* __restrict__ rq, const float* __restrict__ upd,
    const float* __restrict__ whz, float* __restrict__ Qout) {
    __shared__ float Us[32][17];
    __shared__ float Rs[16][32];
    const int bm = blockIdx.x * 32;
    const int bn = blockIdx.y * 32;
    const int tid = threadIdx.x;
    const int tx = tid & 15, ty = tid >> 4;
    const int m0 = ty * 2, n0 = tx * 2;
    const int lrow = tid >> 3;
    const int lkk = (tid & 7) * 2;
    const int qk = tid >> 4;
    const int qn = (tid & 15) * 2;

    float c00 = 0.f, c01 = 0.f, c10 = 0.f, c11 = 0.f;
    for (int k0 = 0; k0 < F; k0 += 16) {
        {
            float2 u = *(const float2*)(Uh + (size_t)(bm + lrow) * F + k0 + lkk);
            Us[lrow][lkk] = u.x; Us[lrow][lkk + 1] = u.y;
            float2 r = *(const float2*)(rq + (size_t)(k0 + qk) * F + bn + qn);
            Rs[qk][qn] = r.x; Rs[qk][qn + 1] = r.y;
        }
        __syncthreads();
#pragma unroll
        for (int k = 0; k < 16; k++) {
            float u0 = Us[m0][k], u1 = Us[m0 + 1][k];
            float r0 = Rs[k][n0], r1 = Rs[k][n0 + 1];
            c00 += u0 * r0; c01 += u0 * r1;
            c10 += u1 * r0; c11 += u1 * r1;
        }
        __syncthreads();
    }
    float c[2][2] = {{c00, c01}, {c10, c11}};
#pragma unroll
    for (int i = 0; i < 2; i++)
#pragma unroll
        for (int j = 0; j < 2; j++) {
            const size_t idx = (size_t)(bm + m0 + i) * F + bn + n0 + j;
            float hc = tanhf(c[i][j] + whz[idx]);
            float u_ = upd[idx];
            Qout[idx] = (1.f - u_) * Q[idx] + u_ * hc;
        }
}

// ---------------- generic SGEMM: C = [relu](A @ B), optional transposed store --
__global__ void __launch_bounds__(256) sgemm_kernel(const float* __restrict__ A,
                                                    const float* __restrict__ B,
                                                    float* __restrict__ C,
                                                    int M, int N, int K, int do_relu,
                                                    int transC, int ldc) {
    __shared__ float As[16][128];
    __shared__ float Bs[16][64];
    const int bm = blockIdx.y * 128;
    const int bn = blockIdx.x * 64;
    const int tid = threadIdx.x;
    const int tx = tid & 15;
    const int ty = tid >> 4;

    float acc[8][4];
#pragma unroll
    for (int i = 0; i < 8; i++)
#pragma unroll
        for (int j = 0; j < 4; j++) acc[i][j] = 0.f;

    const int arow0 = tid >> 2;
    const int akk = (tid & 3) << 2;
    const int brow = tid >> 4;
    const int bnn = (tid & 15) << 2;

    for (int k0 = 0; k0 < K; k0 += 16) {
#pragma unroll
        for (int i = 0; i < 2; i++) {
            const int row = arow0 + i * 64;
            float4 v = *(const float4*)(A + (size_t)(bm + row) * K + (k0 + akk));
            As[akk + 0][row] = v.x;
            As[akk + 1][row] = v.y;
            As[akk + 2][row] = v.z;
            As[akk + 3][row] = v.w;
        }
        {
            float4 v = *(const float4*)(B + (size_t)(k0 + brow) * N + (bn + bnn));
            *(float4*)(&Bs[brow][bnn]) = v;
        }
        __syncthreads();
#pragma unroll
        for (int k = 0; k < 16; k++) {
            float4 a0 = *(const float4*)(&As[k][ty * 8]);
            float4 a1 = *(const float4*)(&As[k][ty * 8 + 4]);
            float4 bv = *(const float4*)(&Bs[k][tx * 4]);
            float a[8] = {a0.x, a0.y, a0.z, a0.w, a1.x, a1.y, a1.z, a1.w};
            float b[4] = {bv.x, bv.y, bv.z, bv.w};
#pragma unroll
            for (int i = 0; i < 8; i++)
#pragma unroll
                for (int j = 0; j < 4; j++) acc[i][j] += a[i] * b[j];
        }
        __syncthreads();
    }
    if (!transC) {
#pragma unroll
        for (int i = 0; i < 8; i++) {
            float4 v;
            v.x = acc[i][0]; v.y = acc[i][1]; v.z = acc[i][2]; v.w = acc[i][3];
            if (do_relu) {
                v.x = fmaxf(v.x, 0.f); v.y = fmaxf(v.y, 0.f);
                v.z = fmaxf(v.z, 0.f); v.w = fmaxf(v.w, 0.f);
            }
            *(float4*)(C + (size_t)(bm + ty * 8 + i) * ldc + bn + tx * 4) = v;
        }
    } else {
#pragma unroll
        for (int j = 0; j < 4; j++) {
            float4 v0, v1;
            v0.x = acc[0][j]; v0.y = acc[1][j]; v0.z = acc[2][j]; v0.w = acc[3][j];
            v1.x = acc[4][j]; v1.y = acc[5][j]; v1.z = acc[6][j]; v1.w = acc[7][j];
            if (do_relu) {
                v0.x = fmaxf(v0.x, 0.f); v0.y = fmaxf(v0.y, 0.f);
                v0.z = fmaxf(v0.z, 0.f); v0.w = fmaxf(v0.w, 0.f);
                v1.x = fmaxf(v1.x, 0.f); v1.y = fmaxf(v1.y, 0.f);
                v1.z = fmaxf(v1.z, 0.f); v1.w = fmaxf(v1.w, 0.f);
            }
            float* Cp = C + (size_t)(bn + tx * 4 + j) * ldc + bm + ty * 8;
            *(float4*)(Cp) = v0;
            *(float4*)(Cp + 4) = v1;
        }
    }
}

// ---------------- orchestration ----------------
extern "C" void kernel_launch(void* const* d_in, const int* in_sizes, int n_in,
                              void* d_out, int out_size) {
    const float* in[25];
    for (int i = 0; i < 25; i++) in[i] = (const float*)d_in[i];
    const float* A = in[0];
    const float* X = in[1];
    // 3: l0_scorer, 4..13: l0 Wz Uz bz Wr Ur br Wh Uh bh Q0
    // 14: l1_scorer, 15..24: l1 Wz Uz bz Wr Ur br Wh Uh bh Q0

    float *Qb, *Pb, *Eb, *tv0, *tv1, *updb, *rqb, *whzb, *Yt, *h1, *Xt;
    cudaGetSymbolAddress((void**)&Qb, g_Q);
    cudaGetSymbolAddress((void**)&Pb, g_P);
    cudaGetSymbolAddress((void**)&Eb, g_E);
    cudaGetSymbolAddress((void**)&tv0, g_tv0);
    cudaGetSymbolAddress((void**)&tv1, g_tv);
    cudaGetSymbolAddress((void**)&updb, g_upd);
    cudaGetSymbolAddress((void**)&rqb, g_rq);
    cudaGetSymbolAddress((void**)&whzb, g_whz);
    cudaGetSymbolAddress((void**)&Yt, g_Yt);
    cudaGetSymbolAddress((void**)&h1, g_h1);
    cudaGetSymbolAddress((void**)&Xt, g_Xt);

    sn_kernel<<<2, 256>>>(in[3], in[14]);
    // transpose X[t] for t=0..6 (B operand of the P GEMMs)
    transpose_kernel<<<dim3(128, 8, 7), 256>>>(X, Xt);
    // batched P[t] = A[t][0:256,:] @ X[t]  (tf32 3x-split tensor path)
    tf32_gemm_kernel<<<dim3(4, 2, 7), 256>>>(A, (size_t)NN * NN, Xt, (size_t)F * NN,
                                             Pb, (size_t)F * F, NN, 0);
    tval_kernel<<<dim3(32, TT), 256>>>(X, (size_t)NN * F, in[3], 0, tv0);

    for (int t = 0; t < TT; t++) {
        const float* embs0 = X + (size_t)t * NN * F;
        const float* q0in = (t == 0) ? in[13] : Qb + (size_t)(0 * 2 + ((t - 1) & 1)) * F * F;
        float* q0out = Qb + (size_t)(0 * 2 + (t & 1)) * F * F;
        const float* q1in = (t == 0) ? in[24] : Qb + (size_t)(2 + ((t - 1) & 1)) * F * F;
        float* q1out = Qb + (size_t)(2 + (t & 1)) * F * F;

        // ---- layer 0 GRU ----
        stage1_kernel<<<dim3(8, 8, 3), 256>>>(in[4], in[5], in[6], in[7], in[8], in[9],
                                              in[10], in[12], embs0, tv0 + t * F, q0in,
                                              updb, rqb, whzb);
        stage2_kernel<<<dim3(8, 8), 256>>>(in[11], q0in, rqb, updb, whzb, q0out);

        if (t < TT - 1) {
            prep1_kernel<<<64, 256>>>(Pb + (size_t)t * F * F, q0out, in[14], Eb, tv1);
            stage1_kernel<<<dim3(8, 8, 3), 256>>>(in[15], in[16], in[17], in[18], in[19],
                                                  in[20], in[21], in[23], Eb, tv1, q1in,
                                                  updb, rqb, whzb);
            stage2_kernel<<<dim3(8, 8), 256>>>(in[22], q1in, rqb, updb, whzb, q1out);
        } else {
            const float* At = A + (size_t)t * NN * NN;
            // Y0t = (X7 @ Q0)^T  [256, 4096]
            sgemm_kernel<<<dim3(4, 32), 256>>>(embs0, q0out, Yt, NN, F, F, 0, 1, NN);
            // h1 = relu(A7 @ Y0)  via tf32 3x-split mma.sync
            tf32_gemm_kernel<<<dim3(4, 32, 1), 256>>>(At, 0, Yt, 0, h1, 0, NN, 1);
            // layer-1 GRU from h1
            tval_kernel<<<dim3(32, 1), 256>>>(h1, 0, in[14], 1, tv1);
            stage1_kernel<<<dim3(8, 8, 3), 256>>>(in[15], in[16], in[17], in[18], in[19],
                                                  in[20], in[21], in[23], h1, tv1, q1in,
                                                  updb, rqb, whzb);
            stage2_kernel<<<dim3(8, 8), 256>>>(in[22], q1in, rqb, updb, whzb, q1out);
            // Y1t = (h1 @ Q1)^T, out = relu(A7 @ Y1)
            sgemm_kernel<<<dim3(4, 32), 256>>>(h1, q1out, Yt, NN, F, F, 0, 1, NN);
            tf32_gemm_kernel<<<dim3(4, 32, 1), 256>>>(At, 0, Yt, 0, (float*)d_out, 0, NN, 1);
        }
    }
}